// round 2
// baseline (speedup 1.0000x reference)
#include <cuda_runtime.h>
#include <cstdint>

#define NN 100000
#define NE 3200000

// ---------------- scratch (device globals; no allocation allowed) ----------
__device__ __align__(16) float g_deg[NN];
__device__ __align__(16) float g_dinv[NN];
__device__ __align__(16) float g_norm[NE];
__device__ __align__(16) int   g_row[NE];
__device__ __align__(16) int   g_col[NE];
__device__ int g_is64;

__device__ __align__(16) float g_t1[NN * 32];   // x @ W1
__device__ __align__(16) float g_a1[NN * 32];   // scatter accumulator L1
__device__ __align__(16) float g_h1[NN * 32];   // elu output L1
__device__ __align__(16) float g_t2[NN * 64];
__device__ __align__(16) float g_a2[NN * 64];
__device__ __align__(16) float g_h2[NN * 64];
__device__ __align__(16) float g_t3[NN * 128];

// ---------------- dtype detect: int64 vs int32 edge_index -----------------
// If buffer is little-endian int64 with values < 2^31, every odd 32-bit word
// is zero. Under an int32 layout, odd words are random node indices (~never 0).
__global__ void k_detect(const int* __restrict__ ei32) {
    __shared__ int cnt;
    if (threadIdx.x == 0) cnt = 0;
    __syncthreads();
    int zeros = 0;
    for (int i = threadIdx.x; i < 1024; i += blockDim.x)
        if (ei32[2 * i + 1] == 0) zeros++;
    atomicAdd(&cnt, zeros);
    __syncthreads();
    if (threadIdx.x == 0) g_is64 = (cnt > 900) ? 1 : 0;
}

// ---------------- prep: deg init, index convert, deg atomic ---------------
__global__ void k_init_deg(int n) {
    int i = blockIdx.x * blockDim.x + threadIdx.x;
    if (i < n) g_deg[i] = 1.0f;   // self-loop weight 1 folded in
}

__global__ void k_prep(const int* __restrict__ ei32,
                       const float* __restrict__ ea, int E, int n) {
    int e = blockIdx.x * blockDim.x + threadIdx.x;
    if (e >= E) return;
    int r, c;
    if (g_is64) {                       // int64 layout: low word holds value
        r = ei32[2 * (long long)e];
        c = ei32[2 * ((long long)E + e)];
    } else {                            // int32 layout
        r = ei32[e];
        c = ei32[E + e];
    }
    // sanitize: degrade to wrong-but-measurable rather than crash
    if ((unsigned)r >= (unsigned)n) r = 0;
    if ((unsigned)c >= (unsigned)n) c = 0;
    g_row[e] = r;
    g_col[e] = c;
    atomicAdd(&g_deg[c], ea[e]);
}

__global__ void k_dinv(int n) {
    int i = blockIdx.x * blockDim.x + threadIdx.x;
    if (i >= n) return;
    float d = g_deg[i];
    g_dinv[i] = (d > 0.0f) ? rsqrtf(fmaxf(d, 1e-30f)) : 0.0f;
}

__global__ void k_norm(const float* __restrict__ ea, int E) {
    int e = blockIdx.x * blockDim.x + threadIdx.x;
    if (e >= E) return;
    g_norm[e] = g_dinv[g_row[e]] * ea[e] * g_dinv[g_col[e]];
}

// ---------------- small dense GEMM: Y[n,FOUT] = X[n,FIN] @ W[FIN,FOUT] -----
template <int FIN, int FOUT, int NPB>
__global__ void k_gemm(const float* __restrict__ X, const float* __restrict__ W,
                       float* __restrict__ Y, int n) {
    __shared__ float Ws[FIN * FOUT];
    __shared__ float Xs[NPB * FIN];
    const int tid = threadIdx.x;
    const int node0 = blockIdx.x * NPB;

    for (int i = tid; i < FIN * FOUT; i += blockDim.x) Ws[i] = W[i];
    for (int i = tid; i < NPB * FIN; i += blockDim.x) {
        int nn = node0 + i / FIN;
        Xs[i] = (nn < n) ? X[(long long)nn * FIN + (i % FIN)] : 0.0f;
    }
    __syncthreads();

    const int ln = tid / FOUT;
    const int f  = tid % FOUT;
    const int node = node0 + ln;
    if (node >= n) return;

    float acc = 0.0f;
#pragma unroll 8
    for (int k = 0; k < FIN; k++) acc += Xs[ln * FIN + k] * Ws[k * FOUT + f];
    Y[(long long)node * FOUT + f] = acc;
}

// ---------------- edge scatter: out[col] += h[row] * norm -----------------
// One edge handled by F/4 lanes; each lane does a float4 gather + vector RED.
template <int F>
__global__ void k_scatter(const float* __restrict__ h, float* __restrict__ out,
                          int E) {
    constexpr int LPE = F / 4;                    // lanes per edge (8/16/32)
    const long long tid = (long long)blockIdx.x * blockDim.x + threadIdx.x;
    const long long e = tid / LPE;
    const int s = (int)(tid % LPE);
    if (e >= E) return;

    const int r = g_row[e];
    const int c = g_col[e];
    const float w = g_norm[e];

    const float4 v = *(const float4*)(h + (long long)r * F + s * 4);
    float* dst = out + (long long)c * F + s * 4;
    asm volatile("red.global.add.v4.f32 [%0], {%1, %2, %3, %4};"
                 :: "l"(dst), "f"(v.x * w), "f"(v.y * w), "f"(v.z * w), "f"(v.w * w)
                 : "memory");
}

// ---------------- pointwise: out = [elu](acc + t*dinv^2 + b) --------------
template <int F, bool DOELU>
__global__ void k_pointwise(const float* __restrict__ acc,
                            const float* __restrict__ t,
                            const float* __restrict__ b,
                            float* __restrict__ out, int n) {
    const long long idx = (long long)blockIdx.x * blockDim.x + threadIdx.x;
    if (idx >= (long long)n * F) return;
    const int i = (int)(idx / F);
    const int f = (int)(idx % F);
    const float dv = g_dinv[i];
    float v = acc[idx] + t[idx] * dv * dv + b[f];
    if (DOELU) v = (v > 0.0f) ? v : expm1f(v);
    out[idx] = v;
}

// ---------------- launch ---------------------------------------------------
static inline int cdiv(long long a, int b) { return (int)((a + b - 1) / b); }

extern "C" void kernel_launch(void* const* d_in, const int* in_sizes, int n_in,
                              void* d_out, int out_size) {
    const float* x  = (const float*)d_in[0];
    const int*   ei = (const int*)d_in[1];
    const float* ea = (const float*)d_in[2];
    const float* W1 = (const float*)d_in[3];
    const float* b1 = (const float*)d_in[4];
    const float* W2 = (const float*)d_in[5];
    const float* b2 = (const float*)d_in[6];
    const float* W3 = (const float*)d_in[7];
    const float* b3 = (const float*)d_in[8];
    float* out = (float*)d_out;

    const int n = in_sizes[0] / 128;   // 100000
    const int E = in_sizes[2];         // 3200000

    void *p_t1, *p_a1, *p_h1, *p_t2, *p_a2, *p_h2, *p_t3;
    cudaGetSymbolAddress(&p_t1, g_t1);
    cudaGetSymbolAddress(&p_a1, g_a1);
    cudaGetSymbolAddress(&p_h1, g_h1);
    cudaGetSymbolAddress(&p_t2, g_t2);
    cudaGetSymbolAddress(&p_a2, g_a2);
    cudaGetSymbolAddress(&p_h2, g_h2);
    cudaGetSymbolAddress(&p_t3, g_t3);

    const int T = 256;

    // --- normalization prep ---
    k_detect<<<1, 256>>>(ei);
    k_init_deg<<<cdiv(n, T), T>>>(n);
    k_prep<<<cdiv(E, T), T>>>(ei, ea, E, n);
    k_dinv<<<cdiv(n, T), T>>>(n);
    k_norm<<<cdiv(E, T), T>>>(ea, E);

    // --- layer 1: 128 -> 32 ---
    cudaMemsetAsync(p_a1, 0, (size_t)n * 32 * sizeof(float));
    k_gemm<128, 32, 8><<<cdiv(n, 8), 256>>>(x, W1, (float*)p_t1, n);
    k_scatter<32><<<cdiv((long long)E * 8, T), T>>>((const float*)p_t1, (float*)p_a1, E);
    k_pointwise<32, true><<<cdiv((long long)n * 32, T), T>>>(
        (const float*)p_a1, (const float*)p_t1, b1, (float*)p_h1, n);

    // --- layer 2: 32 -> 64 ---
    cudaMemsetAsync(p_a2, 0, (size_t)n * 64 * sizeof(float));
    k_gemm<32, 64, 4><<<cdiv(n, 4), 256>>>((const float*)p_h1, W2, (float*)p_t2, n);
    k_scatter<64><<<cdiv((long long)E * 16, T), T>>>((const float*)p_t2, (float*)p_a2, E);
    k_pointwise<64, true><<<cdiv((long long)n * 64, T), T>>>(
        (const float*)p_a2, (const float*)p_t2, b2, (float*)p_h2, n);

    // --- layer 3: 64 -> 128 (accumulate into d_out) ---
    cudaMemsetAsync(out, 0, (size_t)n * 128 * sizeof(float));
    k_gemm<64, 128, 2><<<cdiv(n, 2), 256>>>((const float*)p_h2, W3, (float*)p_t3, n);
    k_scatter<128><<<cdiv((long long)E * 32, T), T>>>((const float*)p_t3, out, E);
    k_pointwise<128, false><<<cdiv((long long)n * 128, T), T>>>(
        out, (const float*)p_t3, b3, out, n);
}

// round 3
// speedup vs baseline: 2.3827x; 2.3827x over previous
#include <cuda_runtime.h>
#include <cstdint>

#define NN 100000
#define NE 3200000

// ---------------- scratch (device globals; no allocation allowed) ----------
__device__ __align__(16) float g_deg[NN];
__device__ __align__(16) float g_dinv[NN];
__device__ __align__(16) int   g_row[NE];
__device__ __align__(16) int   g_col[NE];
__device__ __align__(16) int   g_cnt[NN];       // in-degree (excl self-loop)
__device__ __align__(16) int   g_off[NN];       // exclusive scan of cnt
__device__ __align__(16) int   g_cur[NN];       // fill cursor
__device__ __align__(16) int   g_bsum[512];     // block sums for scan
__device__ int g_is64;

__device__ __align__(16) int   g_srow[NE];      // CSR: source node per slot
__device__ __align__(16) float g_snorm[NE];     // CSR: edge norm per slot

__device__ __align__(16) float g_t1[NN * 32];   // x @ W1
__device__ __align__(16) float g_h1[NN * 32];   // layer-1 output
__device__ __align__(16) float g_t2[NN * 64];
__device__ __align__(16) float g_h2[NN * 64];
__device__ __align__(16) float g_t3[NN * 128];

// ---------------- dtype detect: int64 vs int32 edge_index -----------------
__global__ void k_detect(const int* __restrict__ ei32) {
    __shared__ int cnt;
    if (threadIdx.x == 0) cnt = 0;
    __syncthreads();
    int zeros = 0;
    for (int i = threadIdx.x; i < 1024; i += blockDim.x)
        if (ei32[2 * i + 1] == 0) zeros++;
    atomicAdd(&cnt, zeros);
    __syncthreads();
    if (threadIdx.x == 0) g_is64 = (cnt > 900) ? 1 : 0;
}

// ---------------- prep ------------------------------------------------------
__global__ void k_init_deg(int n) {
    int i = blockIdx.x * blockDim.x + threadIdx.x;
    if (i < n) g_deg[i] = 1.0f;   // self-loop weight 1
}

__global__ void k_prep(const int* __restrict__ ei32,
                       const float* __restrict__ ea, int E, int n) {
    int e = blockIdx.x * blockDim.x + threadIdx.x;
    if (e >= E) return;
    int r, c;
    if (g_is64) {
        r = ei32[2 * (long long)e];
        c = ei32[2 * ((long long)E + e)];
    } else {
        r = ei32[e];
        c = ei32[E + e];
    }
    if ((unsigned)r >= (unsigned)n) r = 0;
    if ((unsigned)c >= (unsigned)n) c = 0;
    g_row[e] = r;
    g_col[e] = c;
    atomicAdd(&g_deg[c], ea[e]);
    atomicAdd(&g_cnt[c], 1);
}

__global__ void k_dinv(int n) {
    int i = blockIdx.x * blockDim.x + threadIdx.x;
    if (i >= n) return;
    float d = g_deg[i];
    g_dinv[i] = (d > 0.0f) ? rsqrtf(fmaxf(d, 1e-30f)) : 0.0f;
}

// ---------------- 3-kernel exclusive scan of g_cnt -> g_off ----------------
__global__ void k_scan1(int n) {                 // 256 threads/block
    __shared__ int sh[256];
    const int t = threadIdx.x;
    const int i = blockIdx.x * 256 + t;
    int v = (i < n) ? g_cnt[i] : 0;
    sh[t] = v;
    __syncthreads();
    for (int d = 1; d < 256; d <<= 1) {
        int u = (t >= d) ? sh[t - d] : 0;
        __syncthreads();
        sh[t] += u;
        __syncthreads();
    }
    if (i < n) g_off[i] = sh[t] - v;             // exclusive, block-local
    if (t == 255) g_bsum[blockIdx.x] = sh[255];
}

__global__ void k_scan2(int nb) {                // 1 block, 512 threads
    __shared__ int sh[512];
    const int t = threadIdx.x;
    int v = (t < nb) ? g_bsum[t] : 0;
    sh[t] = v;
    __syncthreads();
    for (int d = 1; d < 512; d <<= 1) {
        int u = (t >= d) ? sh[t - d] : 0;
        __syncthreads();
        sh[t] += u;
        __syncthreads();
    }
    if (t < nb) g_bsum[t] = sh[t] - v;           // exclusive block offsets
}

__global__ void k_scan3(int n) {
    int i = blockIdx.x * 256 + threadIdx.x;
    if (i < n) g_off[i] += g_bsum[blockIdx.x];
}

// ---------------- CSR fill (order within segment arbitrary) ----------------
__global__ void k_fill(const float* __restrict__ ea, int E) {
    int e = blockIdx.x * blockDim.x + threadIdx.x;
    if (e >= E) return;
    const int r = g_row[e];
    const int c = g_col[e];
    const int pos = g_off[c] + atomicAdd(&g_cur[c], 1);
    g_srow[pos]  = r;
    g_snorm[pos] = g_dinv[r] * ea[e] * g_dinv[c];
}

// ---------------- small dense GEMM: Y[n,FOUT] = X[n,FIN] @ W[FIN,FOUT] -----
template <int FIN, int FOUT, int NPB>
__global__ void k_gemm(const float* __restrict__ X, const float* __restrict__ W,
                       float* __restrict__ Y, int n) {
    __shared__ float Ws[FIN * FOUT];
    __shared__ float Xs[NPB * FIN];
    const int tid = threadIdx.x;
    const int node0 = blockIdx.x * NPB;

    for (int i = tid; i < FIN * FOUT; i += blockDim.x) Ws[i] = W[i];
    for (int i = tid; i < NPB * FIN; i += blockDim.x) {
        int nn = node0 + i / FIN;
        Xs[i] = (nn < n) ? X[(long long)nn * FIN + (i % FIN)] : 0.0f;
    }
    __syncthreads();

    const int ln = tid / FOUT;
    const int f  = tid % FOUT;
    const int node = node0 + ln;
    if (node >= n) return;

    float acc = 0.0f;
#pragma unroll 8
    for (int k = 0; k < FIN; k++) acc += Xs[ln * FIN + k] * Ws[k * FOUT + f];
    Y[(long long)node * FOUT + f] = acc;
}

// ---------------- fused aggregate + self-loop + bias + ELU -----------------
// F/4 lanes per node; each lane owns a float4 slice. Register accumulation,
// single write. 4-way unrolled edge loop for MLP.
template <int F, bool DOELU>
__global__ void k_agg(const float* __restrict__ t, const float* __restrict__ b,
                      float* __restrict__ out, int n) {
    constexpr int LPE = F / 4;
    const long long tid = (long long)blockIdx.x * blockDim.x + threadIdx.x;
    const int node = (int)(tid / LPE);
    const int s = (int)(tid % LPE);
    if (node >= n) return;

    const int base = g_off[node];
    const int deg  = g_cnt[node];

    float ax = 0.f, ay = 0.f, az = 0.f, aw = 0.f;
    int k = 0;
    for (; k + 4 <= deg; k += 4) {
        const int   r0 = g_srow[base + k],     r1 = g_srow[base + k + 1];
        const int   r2 = g_srow[base + k + 2], r3 = g_srow[base + k + 3];
        const float w0 = g_snorm[base + k],     w1 = g_snorm[base + k + 1];
        const float w2 = g_snorm[base + k + 2], w3 = g_snorm[base + k + 3];
        const float4 v0 = *(const float4*)(t + (long long)r0 * F + s * 4);
        const float4 v1 = *(const float4*)(t + (long long)r1 * F + s * 4);
        const float4 v2 = *(const float4*)(t + (long long)r2 * F + s * 4);
        const float4 v3 = *(const float4*)(t + (long long)r3 * F + s * 4);
        ax += v0.x * w0 + v1.x * w1 + v2.x * w2 + v3.x * w3;
        ay += v0.y * w0 + v1.y * w1 + v2.y * w2 + v3.y * w3;
        az += v0.z * w0 + v1.z * w1 + v2.z * w2 + v3.z * w3;
        aw += v0.w * w0 + v1.w * w1 + v2.w * w2 + v3.w * w3;
    }
    for (; k < deg; k++) {
        const int   r0 = g_srow[base + k];
        const float w0 = g_snorm[base + k];
        const float4 v0 = *(const float4*)(t + (long long)r0 * F + s * 4);
        ax += v0.x * w0; ay += v0.y * w0; az += v0.z * w0; aw += v0.w * w0;
    }

    // self-loop + bias
    float dv = g_dinv[node]; dv *= dv;
    const float4 tv = *(const float4*)(t + (long long)node * F + s * 4);
    ax += tv.x * dv + b[s * 4 + 0];
    ay += tv.y * dv + b[s * 4 + 1];
    az += tv.z * dv + b[s * 4 + 2];
    aw += tv.w * dv + b[s * 4 + 3];

    if (DOELU) {
        ax = (ax > 0.f) ? ax : expm1f(ax);
        ay = (ay > 0.f) ? ay : expm1f(ay);
        az = (az > 0.f) ? az : expm1f(az);
        aw = (aw > 0.f) ? aw : expm1f(aw);
    }
    float4 o; o.x = ax; o.y = ay; o.z = az; o.w = aw;
    *(float4*)(out + (long long)node * F + s * 4) = o;
}

// ---------------- launch ---------------------------------------------------
static inline int cdiv(long long a, int b) { return (int)((a + b - 1) / b); }

extern "C" void kernel_launch(void* const* d_in, const int* in_sizes, int n_in,
                              void* d_out, int out_size) {
    const float* x  = (const float*)d_in[0];
    const int*   ei = (const int*)d_in[1];
    const float* ea = (const float*)d_in[2];
    const float* W1 = (const float*)d_in[3];
    const float* b1 = (const float*)d_in[4];
    const float* W2 = (const float*)d_in[5];
    const float* b2 = (const float*)d_in[6];
    const float* W3 = (const float*)d_in[7];
    const float* b3 = (const float*)d_in[8];
    float* out = (float*)d_out;

    const int n = in_sizes[0] / 128;   // 100000
    const int E = in_sizes[2];         // 3200000

    void *p_cnt, *p_cur, *p_t1, *p_h1, *p_t2, *p_h2, *p_t3;
    cudaGetSymbolAddress(&p_cnt, g_cnt);
    cudaGetSymbolAddress(&p_cur, g_cur);
    cudaGetSymbolAddress(&p_t1, g_t1);
    cudaGetSymbolAddress(&p_h1, g_h1);
    cudaGetSymbolAddress(&p_t2, g_t2);
    cudaGetSymbolAddress(&p_h2, g_h2);
    cudaGetSymbolAddress(&p_t3, g_t3);

    const int T = 256;
    const int nb = cdiv(n, 256);       // 391 scan blocks (<=512)

    // --- prep: degrees, dinv, CSR build ---
    cudaMemsetAsync(p_cnt, 0, (size_t)n * sizeof(int));
    cudaMemsetAsync(p_cur, 0, (size_t)n * sizeof(int));
    k_detect<<<1, 256>>>(ei);
    k_init_deg<<<cdiv(n, T), T>>>(n);
    k_prep<<<cdiv(E, T), T>>>(ei, ea, E, n);
    k_dinv<<<cdiv(n, T), T>>>(n);
    k_scan1<<<nb, 256>>>(n);
    k_scan2<<<1, 512>>>(nb);
    k_scan3<<<nb, 256>>>(n);
    k_fill<<<cdiv(E, T), T>>>(ea, E);

    // --- layer 1: 128 -> 32 ---
    k_gemm<128, 32, 8><<<cdiv(n, 8), 256>>>(x, W1, (float*)p_t1, n);
    k_agg<32, true><<<cdiv((long long)n * 8, T), T>>>(
        (const float*)p_t1, b1, (float*)p_h1, n);

    // --- layer 2: 32 -> 64 ---
    k_gemm<32, 64, 4><<<cdiv(n, 4), 256>>>((const float*)p_h1, W2, (float*)p_t2, n);
    k_agg<64, true><<<cdiv((long long)n * 16, T), T>>>(
        (const float*)p_t2, b2, (float*)p_h2, n);

    // --- layer 3: 64 -> 128 ---
    k_gemm<64, 128, 2><<<cdiv(n, 2), 256>>>((const float*)p_h2, W3, (float*)p_t3, n);
    k_agg<128, false><<<cdiv((long long)n * 32, T), T>>>(
        (const float*)p_t3, b3, out, n);
}

// round 5
// speedup vs baseline: 2.6917x; 1.1297x over previous
#include <cuda_runtime.h>
#include <cuda_fp16.h>
#include <cstdint>

#define NN 100000
#define NE 3200000

// ---------------- scratch (device globals; no allocation allowed) ----------
__device__ __align__(16) float g_deg[NN];
__device__ __align__(16) float g_dinv[NN];
__device__ __align__(16) int   g_cnt[NN];       // in-degree (excl self-loop)
__device__ __align__(16) int   g_off[NN];       // exclusive scan of cnt
__device__ __align__(16) int   g_cur[NN];       // fill cursor (copy of off)
__device__ __align__(16) int   g_bsum[512];     // block sums for scan
__device__ int g_is64;

__device__ __align__(16) uint2 g_edge[NE];      // CSR payload: {src, norm bits}

__device__ __align__(16) float  g_t1f[NN * 32]; // x @ W1 (fp32, self terms)
__device__ __align__(16) __half g_t1h[NN * 32]; // x @ W1 (fp16, gather)
__device__ __align__(16) float  g_h1f[NN * 32]; // elu layer-1 out
__device__ __align__(16) __half g_h1h[NN * 32];
__device__ __align__(16) float  g_s2 [NN * 32]; // A @ h1
__device__ __align__(16) float  g_h2f[NN * 64]; // elu layer-2 out
__device__ __align__(16) __half g_h2h[NN * 64];
__device__ __align__(16) float  g_s3 [NN * 64]; // A @ h2

// ---------------- dtype detect: int64 vs int32 edge_index -----------------
__global__ void k_detect(const int* __restrict__ ei32) {
    __shared__ int cnt;
    if (threadIdx.x == 0) cnt = 0;
    __syncthreads();
    int zeros = 0;
    for (int i = threadIdx.x; i < 1024; i += blockDim.x)
        if (ei32[2 * i + 1] == 0) zeros++;
    atomicAdd(&cnt, zeros);
    __syncthreads();
    if (threadIdx.x == 0) g_is64 = (cnt > 900) ? 1 : 0;
}

__device__ __forceinline__ void load_edge(const int* __restrict__ ei32,
                                          int e, int E, int n, int& r, int& c) {
    if (g_is64) {
        r = ei32[2 * (long long)e];
        c = ei32[2 * ((long long)E + e)];
    } else {
        r = ei32[e];
        c = ei32[E + e];
    }
    if ((unsigned)r >= (unsigned)n) r = 0;
    if ((unsigned)c >= (unsigned)n) c = 0;
}

// ---------------- prep ------------------------------------------------------
__global__ void k_init_deg(int n) {
    int i = blockIdx.x * blockDim.x + threadIdx.x;
    if (i < n) g_deg[i] = 1.0f;   // self-loop weight 1
}

__global__ void k_prep(const int* __restrict__ ei32,
                       const float* __restrict__ ea, int E, int n) {
    int e = blockIdx.x * blockDim.x + threadIdx.x;
    if (e >= E) return;
    int r, c;
    load_edge(ei32, e, E, n, r, c);
    atomicAdd(&g_deg[c], ea[e]);
    atomicAdd(&g_cnt[c], 1);
}

__global__ void k_dinv(int n) {
    int i = blockIdx.x * blockDim.x + threadIdx.x;
    if (i >= n) return;
    float d = g_deg[i];
    g_dinv[i] = (d > 0.0f) ? rsqrtf(fmaxf(d, 1e-30f)) : 0.0f;
}

// ---------------- 3-kernel exclusive scan of g_cnt -> g_off ----------------
__global__ void k_scan1(int n) {
    __shared__ int sh[256];
    const int t = threadIdx.x;
    const int i = blockIdx.x * 256 + t;
    int v = (i < n) ? g_cnt[i] : 0;
    sh[t] = v;
    __syncthreads();
    for (int d = 1; d < 256; d <<= 1) {
        int u = (t >= d) ? sh[t - d] : 0;
        __syncthreads();
        sh[t] += u;
        __syncthreads();
    }
    if (i < n) g_off[i] = sh[t] - v;
    if (t == 255) g_bsum[blockIdx.x] = sh[255];
}

__global__ void k_scan2(int nb) {
    __shared__ int sh[512];
    const int t = threadIdx.x;
    int v = (t < nb) ? g_bsum[t] : 0;
    sh[t] = v;
    __syncthreads();
    for (int d = 1; d < 512; d <<= 1) {
        int u = (t >= d) ? sh[t - d] : 0;
        __syncthreads();
        sh[t] += u;
        __syncthreads();
    }
    if (t < nb) g_bsum[t] = sh[t] - v;
}

__global__ void k_scan3(int n) {
    int i = blockIdx.x * 256 + threadIdx.x;
    if (i < n) g_off[i] += g_bsum[blockIdx.x];
}

// ---------------- CSR fill --------------------------------------------------
__global__ void k_fill(const int* __restrict__ ei32,
                       const float* __restrict__ ea, int E, int n) {
    int e = blockIdx.x * blockDim.x + threadIdx.x;
    if (e >= E) return;
    int r, c;
    load_edge(ei32, e, E, n, r, c);
    const int pos = atomicAdd(&g_cur[c], 1);
    const float w = g_dinv[r] * ea[e] * g_dinv[c];
    g_edge[pos] = make_uint2((unsigned)r, __float_as_uint(w));
}

// ---------------- small dense GEMM with fused epilogue ---------------------
// Y[n,FOUT] = X[n,FIN] @ W[FIN,FOUT] (+b, elu); optional dual fp32/fp16 write.
template <int FIN, int FOUT, int NPB, bool BIAS, bool ELU, bool DUALH>
__global__ void k_gemm(const float* __restrict__ X, const float* __restrict__ W,
                       const float* __restrict__ b, float* __restrict__ Yf,
                       __half* __restrict__ Yh, int n) {
    __shared__ float Ws[FIN * FOUT];
    __shared__ float Xs[NPB * FIN];
    const int tid = threadIdx.x;
    const int node0 = blockIdx.x * NPB;

    for (int i = tid; i < FIN * FOUT; i += blockDim.x) Ws[i] = W[i];
    for (int i = tid; i < NPB * FIN; i += blockDim.x) {
        int nn = node0 + i / FIN;
        Xs[i] = (nn < n) ? X[(long long)nn * FIN + (i % FIN)] : 0.0f;
    }
    __syncthreads();

    const int ln = tid / FOUT;
    const int f  = tid % FOUT;
    const int node = node0 + ln;
    if (node >= n) return;

    float acc = 0.0f;
#pragma unroll 8
    for (int k = 0; k < FIN; k++) acc += Xs[ln * FIN + k] * Ws[k * FOUT + f];
    if (BIAS) acc += b[f];
    if (ELU)  acc = (acc > 0.f) ? acc : expm1f(acc);
    Yf[(long long)node * FOUT + f] = acc;
    if (DUALH) Yh[(long long)node * FOUT + f] = __float2half(acc);
}

// ---------------- fused CSR aggregate ---------------------------------------
// out[i] = sum_{e in seg(i)} gh[src(e)]*norm(e) + sf[i]*dinv[i]^2 (+b, elu)
// F/4 lanes per node; lane owns 4 halfs (one 8B load per edge).
template <int F, bool BE, bool DUALH>
__global__ void k_agg(const __half* __restrict__ gh, const float* __restrict__ sf,
                      const float* __restrict__ b, float* __restrict__ outf,
                      __half* __restrict__ outh, int n) {
    constexpr int LPE = F / 4;
    const long long tid = (long long)blockIdx.x * blockDim.x + threadIdx.x;
    const int node = (int)(tid / LPE);
    const int s = (int)(tid % LPE);
    if (node >= n) return;

    const int base = g_off[node];
    const int deg  = g_cnt[node];

    float ax = 0.f, ay = 0.f, az = 0.f, aw = 0.f;
    int k = 0;
#define GATH(ED)                                                               \
    {                                                                          \
        const float w_ = __uint_as_float((ED).y);                              \
        const uint2 raw_ = *(const uint2*)(gh + (size_t)(ED).x * F + s * 4);   \
        const float2 p0_ = __half22float2(*(const __half2*)&raw_.x);           \
        const float2 p1_ = __half22float2(*(const __half2*)&raw_.y);           \
        ax += p0_.x * w_; ay += p0_.y * w_;                                    \
        az += p1_.x * w_; aw += p1_.y * w_;                                    \
    }
    for (; k + 4 <= deg; k += 4) {
        const uint2 e0 = g_edge[base + k],     e1 = g_edge[base + k + 1];
        const uint2 e2 = g_edge[base + k + 2], e3 = g_edge[base + k + 3];
        GATH(e0) GATH(e1) GATH(e2) GATH(e3)
    }
    for (; k < deg; k++) {
        const uint2 e0 = g_edge[base + k];
        GATH(e0)
    }
#undef GATH

    // self-loop (+ bias, elu)
    float dv = g_dinv[node]; dv *= dv;
    const float4 tv = *(const float4*)(sf + (size_t)node * F + s * 4);
    ax += tv.x * dv; ay += tv.y * dv; az += tv.z * dv; aw += tv.w * dv;
    if (BE) {
        ax += b[s * 4 + 0]; ay += b[s * 4 + 1];
        az += b[s * 4 + 2]; aw += b[s * 4 + 3];
        ax = (ax > 0.f) ? ax : expm1f(ax);
        ay = (ay > 0.f) ? ay : expm1f(ay);
        az = (az > 0.f) ? az : expm1f(az);
        aw = (aw > 0.f) ? aw : expm1f(aw);
    }
    float4 o; o.x = ax; o.y = ay; o.z = az; o.w = aw;
    *(float4*)(outf + (size_t)node * F + s * 4) = o;
    if (DUALH) {
        __half2* hp = (__half2*)(outh + (size_t)node * F + s * 4);
        hp[0] = __floats2half2_rn(ax, ay);
        hp[1] = __floats2half2_rn(az, aw);
    }
}

// ---------------- launch ---------------------------------------------------
static inline int cdiv(long long a, int b) { return (int)((a + b - 1) / b); }

extern "C" void kernel_launch(void* const* d_in, const int* in_sizes, int n_in,
                              void* d_out, int out_size) {
    const float* x  = (const float*)d_in[0];
    const int*   ei = (const int*)d_in[1];
    const float* ea = (const float*)d_in[2];
    const float* W1 = (const float*)d_in[3];
    const float* b1 = (const float*)d_in[4];
    const float* W2 = (const float*)d_in[5];
    const float* b2 = (const float*)d_in[6];
    const float* W3 = (const float*)d_in[7];
    const float* b3 = (const float*)d_in[8];
    float* out = (float*)d_out;

    const int n = in_sizes[0] / 128;   // 100000
    const int E = in_sizes[2];         // 3200000

    void *p_cnt, *p_off, *p_cur;
    void *p_t1f, *p_t1h, *p_h1f, *p_h1h, *p_s2, *p_h2f, *p_h2h, *p_s3;
    cudaGetSymbolAddress(&p_cnt, g_cnt);
    cudaGetSymbolAddress(&p_off, g_off);
    cudaGetSymbolAddress(&p_cur, g_cur);
    cudaGetSymbolAddress(&p_t1f, g_t1f);
    cudaGetSymbolAddress(&p_t1h, g_t1h);
    cudaGetSymbolAddress(&p_h1f, g_h1f);
    cudaGetSymbolAddress(&p_h1h, g_h1h);
    cudaGetSymbolAddress(&p_s2,  g_s2);
    cudaGetSymbolAddress(&p_h2f, g_h2f);
    cudaGetSymbolAddress(&p_h2h, g_h2h);
    cudaGetSymbolAddress(&p_s3,  g_s3);

    const int T = 256;
    const int nb = cdiv(n, 256);       // scan blocks (<=512)

    // --- prep: degrees, dinv, CSR build ---
    cudaMemsetAsync(p_cnt, 0, (size_t)n * sizeof(int));
    k_detect<<<1, 256>>>(ei);
    k_init_deg<<<cdiv(n, T), T>>>(n);
    k_prep<<<cdiv(E, T), T>>>(ei, ea, E, n);
    k_dinv<<<cdiv(n, T), T>>>(n);
    k_scan1<<<nb, 256>>>(n);
    k_scan2<<<1, 512>>>(nb);
    k_scan3<<<nb, 256>>>(n);
    cudaMemcpyAsync(p_cur, p_off, (size_t)n * sizeof(int),
                    cudaMemcpyDeviceToDevice);
    k_fill<<<cdiv(E, T), T>>>(ei, ea, E, n);

    // --- layer 1: t1 = x@W1 ; h1 = elu(A t1 + b1) ---
    k_gemm<128, 32, 8, false, false, true><<<cdiv(n, 8), 256>>>(
        x, W1, nullptr, (float*)p_t1f, (__half*)p_t1h, n);
    k_agg<32, true, true><<<cdiv((long long)n * 8, T), T>>>(
        (const __half*)p_t1h, (const float*)p_t1f, b1,
        (float*)p_h1f, (__half*)p_h1h, n);

    // --- layer 2: s2 = A h1 ; h2 = elu(s2@W2 + b2) ---
    k_agg<32, false, false><<<cdiv((long long)n * 8, T), T>>>(
        (const __half*)p_h1h, (const float*)p_h1f, nullptr,
        (float*)p_s2, nullptr, n);
    k_gemm<32, 64, 4, true, true, true><<<cdiv(n, 4), 256>>>(
        (const float*)p_s2, W2, b2, (float*)p_h2f, (__half*)p_h2h, n);

    // --- layer 3: s3 = A h2 ; out = s3@W3 + b3 ---
    k_agg<64, false, false><<<cdiv((long long)n * 16, T), T>>>(
        (const __half*)p_h2h, (const float*)p_h2f, nullptr,
        (float*)p_s3, nullptr, n);
    k_gemm<64, 128, 2, true, false, false><<<cdiv(n, 2), 256>>>(
        (const float*)p_s3, W3, b3, out, nullptr, n);
}

// round 6
// speedup vs baseline: 3.4442x; 1.2795x over previous
#include <cuda_runtime.h>
#include <cuda_fp16.h>
#include <cstdint>

#define NN 100000
#define NE 3200000

// ---------------- scratch (device globals; no allocation allowed) ----------
__device__ __align__(16) float g_deg[NN];
__device__ __align__(16) float g_dinv[NN];
__device__ __align__(16) int   g_cnt[NN];       // in-degree (excl self-loop)
__device__ __align__(16) int   g_off[NN];       // exclusive scan of cnt
__device__ __align__(16) int   g_cur[NN];       // fill cursor (copy of off)
__device__ __align__(16) int   g_bsum[512];     // block sums for scan
__device__ int g_is64;

__device__ __align__(16) uint2 g_edge[NE];      // CSR payload: {src, norm bits}

__device__ __align__(16) float  g_t1f[NN * 32]; // x @ W1 (fp32, self terms)
__device__ __align__(16) __half g_t1h[NN * 32]; // x @ W1 (fp16, gather)
__device__ __align__(16) float  g_h1f[NN * 32]; // elu layer-1 out
__device__ __align__(16) __half g_h1h[NN * 32];
__device__ __align__(16) float  g_s2 [NN * 32]; // A @ h1
__device__ __align__(16) float  g_h2f[NN * 64]; // elu layer-2 out
__device__ __align__(16) __half g_h2h[NN * 64];
__device__ __align__(16) float  g_s3 [NN * 64]; // A @ h2

// ---------------- dtype detect: int64 vs int32 edge_index -----------------
__global__ void k_detect(const int* __restrict__ ei32) {
    __shared__ int cnt;
    if (threadIdx.x == 0) cnt = 0;
    __syncthreads();
    int zeros = 0;
    for (int i = threadIdx.x; i < 1024; i += blockDim.x)
        if (ei32[2 * i + 1] == 0) zeros++;
    atomicAdd(&cnt, zeros);
    __syncthreads();
    if (threadIdx.x == 0) g_is64 = (cnt > 900) ? 1 : 0;
}

__device__ __forceinline__ void load_edge(const int* __restrict__ ei32,
                                          int e, int E, int n, int& r, int& c) {
    if (g_is64) {
        r = ei32[2 * (long long)e];
        c = ei32[2 * ((long long)E + e)];
    } else {
        r = ei32[e];
        c = ei32[E + e];
    }
    if ((unsigned)r >= (unsigned)n) r = 0;
    if ((unsigned)c >= (unsigned)n) c = 0;
}

// ---------------- prep ------------------------------------------------------
__global__ void k_init_deg(int n) {
    int i = blockIdx.x * blockDim.x + threadIdx.x;
    if (i < n) g_deg[i] = 1.0f;   // self-loop weight 1
}

__global__ void k_prep(const int* __restrict__ ei32,
                       const float* __restrict__ ea, int E, int n) {
    int e = blockIdx.x * blockDim.x + threadIdx.x;
    if (e >= E) return;
    int r, c;
    load_edge(ei32, e, E, n, r, c);
    atomicAdd(&g_deg[c], ea[e]);
    atomicAdd(&g_cnt[c], 1);
}

__global__ void k_dinv(int n) {
    int i = blockIdx.x * blockDim.x + threadIdx.x;
    if (i >= n) return;
    float d = g_deg[i];
    g_dinv[i] = (d > 0.0f) ? rsqrtf(fmaxf(d, 1e-30f)) : 0.0f;
}

// ---------------- 3-kernel exclusive scan of g_cnt -> g_off ----------------
__global__ void k_scan1(int n) {
    __shared__ int sh[256];
    const int t = threadIdx.x;
    const int i = blockIdx.x * 256 + t;
    int v = (i < n) ? g_cnt[i] : 0;
    sh[t] = v;
    __syncthreads();
    for (int d = 1; d < 256; d <<= 1) {
        int u = (t >= d) ? sh[t - d] : 0;
        __syncthreads();
        sh[t] += u;
        __syncthreads();
    }
    if (i < n) g_off[i] = sh[t] - v;
    if (t == 255) g_bsum[blockIdx.x] = sh[255];
}

__global__ void k_scan2(int nb) {
    __shared__ int sh[512];
    const int t = threadIdx.x;
    int v = (t < nb) ? g_bsum[t] : 0;
    sh[t] = v;
    __syncthreads();
    for (int d = 1; d < 512; d <<= 1) {
        int u = (t >= d) ? sh[t - d] : 0;
        __syncthreads();
        sh[t] += u;
        __syncthreads();
    }
    if (t < nb) g_bsum[t] = sh[t] - v;
}

__global__ void k_scan3(int n) {
    int i = blockIdx.x * 256 + threadIdx.x;
    if (i < n) g_off[i] += g_bsum[blockIdx.x];
}

// ---------------- CSR fill --------------------------------------------------
__global__ void k_fill(const int* __restrict__ ei32,
                       const float* __restrict__ ea, int E, int n) {
    int e = blockIdx.x * blockDim.x + threadIdx.x;
    if (e >= E) return;
    int r, c;
    load_edge(ei32, e, E, n, r, c);
    const int pos = atomicAdd(&g_cur[c], 1);
    const float w = g_dinv[r] * ea[e] * g_dinv[c];
    g_edge[pos] = make_uint2((unsigned)r, __float_as_uint(w));
}

// ---------------- register-tiled GEMM with fused epilogue -------------------
// Y[n,FOUT] = X[n,FIN] @ W[FIN,FOUT] (+b, elu); optional dual fp32/fp16 write.
// 256 threads; thread tile = 4 nodes x 4 fouts; X staged transposed in smem.
template <int FIN, int FOUT, bool BIAS, bool ELU, bool DUALH>
__global__ void k_gemm(const float* __restrict__ X, const float* __restrict__ W,
                       const float* __restrict__ b, float* __restrict__ Yf,
                       __half* __restrict__ Yh, int n) {
    constexpr int BX   = FOUT / 4;       // threads along f       (8/16/32)
    constexpr int BY   = 256 / BX;       // threads along nodes   (32/16/8)
    constexpr int NPB  = BY * 4;         // nodes per block       (128/64/32)
    constexpr int KC   = 32;             // k-chunk
    constexpr int XSTR = NPB + 1;        // conflict-free transposed stride

    __shared__ float Xs[KC * XSTR];
    __shared__ float Ws[KC * FOUT];

    const int tid = threadIdx.x;
    const int tx = tid % BX;             // f-tile index
    const int ty = tid / BX;             // node-tile index
    const int node0 = blockIdx.x * NPB;

    float acc[4][4] = {};

    for (int ck = 0; ck < FIN; ck += KC) {
        // stage X chunk transposed: Xs[k][local_node]
#pragma unroll
        for (int t = 0; t < NPB * KC / 256; t++) {
            const int idx = t * 256 + tid;
            const int ln = idx / KC;
            const int k  = idx % KC;
            const int node = node0 + ln;
            const float v = (node < n) ? X[(size_t)node * FIN + ck + k] : 0.f;
            Xs[k * XSTR + ln] = v;
        }
        // stage W chunk: Ws[k][f]
#pragma unroll
        for (int t = 0; t < KC * FOUT / 256; t++) {
            const int idx = t * 256 + tid;
            Ws[idx] = W[(size_t)(ck + idx / FOUT) * FOUT + (idx % FOUT)];
        }
        __syncthreads();

#pragma unroll
        for (int k = 0; k < KC; k++) {
            const float4 wv = *(const float4*)&Ws[k * FOUT + tx * 4];
#pragma unroll
            for (int j = 0; j < 4; j++) {
                const float xv = Xs[k * XSTR + ty * 4 + j];
                acc[j][0] += xv * wv.x;
                acc[j][1] += xv * wv.y;
                acc[j][2] += xv * wv.z;
                acc[j][3] += xv * wv.w;
            }
        }
        __syncthreads();
    }

    float4 bv = make_float4(0.f, 0.f, 0.f, 0.f);
    if (BIAS) bv = *(const float4*)&b[tx * 4];

#pragma unroll
    for (int j = 0; j < 4; j++) {
        const int node = node0 + ty * 4 + j;
        if (node >= n) continue;
        float o0 = acc[j][0] + bv.x;
        float o1 = acc[j][1] + bv.y;
        float o2 = acc[j][2] + bv.z;
        float o3 = acc[j][3] + bv.w;
        if (ELU) {
            o0 = (o0 > 0.f) ? o0 : expm1f(o0);
            o1 = (o1 > 0.f) ? o1 : expm1f(o1);
            o2 = (o2 > 0.f) ? o2 : expm1f(o2);
            o3 = (o3 > 0.f) ? o3 : expm1f(o3);
        }
        float4 ov; ov.x = o0; ov.y = o1; ov.z = o2; ov.w = o3;
        *(float4*)(Yf + (size_t)node * FOUT + tx * 4) = ov;
        if (DUALH) {
            __half2* hp = (__half2*)(Yh + (size_t)node * FOUT + tx * 4);
            hp[0] = __floats2half2_rn(o0, o1);
            hp[1] = __floats2half2_rn(o2, o3);
        }
    }
}

// ---------------- fused CSR aggregate ---------------------------------------
// out[i] = sum_{e in seg(i)} gh[src(e)]*norm(e) + sf[i]*dinv[i]^2 (+b, elu)
template <int F, bool BE, bool DUALH>
__global__ void k_agg(const __half* __restrict__ gh, const float* __restrict__ sf,
                      const float* __restrict__ b, float* __restrict__ outf,
                      __half* __restrict__ outh, int n) {
    constexpr int LPE = F / 4;
    const long long tid = (long long)blockIdx.x * blockDim.x + threadIdx.x;
    const int node = (int)(tid / LPE);
    const int s = (int)(tid % LPE);
    if (node >= n) return;

    const int base = g_off[node];
    const int deg  = g_cnt[node];

    float ax = 0.f, ay = 0.f, az = 0.f, aw = 0.f;
    int k = 0;
#define GATH(ED)                                                               \
    {                                                                          \
        const float w_ = __uint_as_float((ED).y);                              \
        const uint2 raw_ = *(const uint2*)(gh + (size_t)(ED).x * F + s * 4);   \
        const float2 p0_ = __half22float2(*(const __half2*)&raw_.x);           \
        const float2 p1_ = __half22float2(*(const __half2*)&raw_.y);           \
        ax += p0_.x * w_; ay += p0_.y * w_;                                    \
        az += p1_.x * w_; aw += p1_.y * w_;                                    \
    }
    for (; k + 4 <= deg; k += 4) {
        const uint2 e0 = g_edge[base + k],     e1 = g_edge[base + k + 1];
        const uint2 e2 = g_edge[base + k + 2], e3 = g_edge[base + k + 3];
        GATH(e0) GATH(e1) GATH(e2) GATH(e3)
    }
    for (; k < deg; k++) {
        const uint2 e0 = g_edge[base + k];
        GATH(e0)
    }
#undef GATH

    float dv = g_dinv[node]; dv *= dv;
    const float4 tv = *(const float4*)(sf + (size_t)node * F + s * 4);
    ax += tv.x * dv; ay += tv.y * dv; az += tv.z * dv; aw += tv.w * dv;
    if (BE) {
        ax += b[s * 4 + 0]; ay += b[s * 4 + 1];
        az += b[s * 4 + 2]; aw += b[s * 4 + 3];
        ax = (ax > 0.f) ? ax : expm1f(ax);
        ay = (ay > 0.f) ? ay : expm1f(ay);
        az = (az > 0.f) ? az : expm1f(az);
        aw = (aw > 0.f) ? aw : expm1f(aw);
    }
    float4 o; o.x = ax; o.y = ay; o.z = az; o.w = aw;
    *(float4*)(outf + (size_t)node * F + s * 4) = o;
    if (DUALH) {
        __half2* hp = (__half2*)(outh + (size_t)node * F + s * 4);
        hp[0] = __floats2half2_rn(ax, ay);
        hp[1] = __floats2half2_rn(az, aw);
    }
}

// ---------------- launch ---------------------------------------------------
static inline int cdiv(long long a, int b) { return (int)((a + b - 1) / b); }

extern "C" void kernel_launch(void* const* d_in, const int* in_sizes, int n_in,
                              void* d_out, int out_size) {
    const float* x  = (const float*)d_in[0];
    const int*   ei = (const int*)d_in[1];
    const float* ea = (const float*)d_in[2];
    const float* W1 = (const float*)d_in[3];
    const float* b1 = (const float*)d_in[4];
    const float* W2 = (const float*)d_in[5];
    const float* b2 = (const float*)d_in[6];
    const float* W3 = (const float*)d_in[7];
    const float* b3 = (const float*)d_in[8];
    float* out = (float*)d_out;

    const int n = in_sizes[0] / 128;   // 100000
    const int E = in_sizes[2];         // 3200000

    void *p_cnt, *p_off, *p_cur;
    void *p_t1f, *p_t1h, *p_h1f, *p_h1h, *p_s2, *p_h2f, *p_h2h, *p_s3;
    cudaGetSymbolAddress(&p_cnt, g_cnt);
    cudaGetSymbolAddress(&p_off, g_off);
    cudaGetSymbolAddress(&p_cur, g_cur);
    cudaGetSymbolAddress(&p_t1f, g_t1f);
    cudaGetSymbolAddress(&p_t1h, g_t1h);
    cudaGetSymbolAddress(&p_h1f, g_h1f);
    cudaGetSymbolAddress(&p_h1h, g_h1h);
    cudaGetSymbolAddress(&p_s2,  g_s2);
    cudaGetSymbolAddress(&p_h2f, g_h2f);
    cudaGetSymbolAddress(&p_h2h, g_h2h);
    cudaGetSymbolAddress(&p_s3,  g_s3);

    const int T = 256;
    const int nb = cdiv(n, 256);

    // --- prep: degrees, dinv, CSR build ---
    cudaMemsetAsync(p_cnt, 0, (size_t)n * sizeof(int));
    k_detect<<<1, 256>>>(ei);
    k_init_deg<<<cdiv(n, T), T>>>(n);
    k_prep<<<cdiv(E, T), T>>>(ei, ea, E, n);
    k_dinv<<<cdiv(n, T), T>>>(n);
    k_scan1<<<nb, 256>>>(n);
    k_scan2<<<1, 512>>>(nb);
    k_scan3<<<nb, 256>>>(n);
    cudaMemcpyAsync(p_cur, p_off, (size_t)n * sizeof(int),
                    cudaMemcpyDeviceToDevice);
    k_fill<<<cdiv(E, T), T>>>(ei, ea, E, n);

    // --- layer 1: t1 = x@W1 ; h1 = elu(A t1 + b1) ---
    k_gemm<128, 32, false, false, true><<<cdiv(n, 128), 256>>>(
        x, W1, nullptr, (float*)p_t1f, (__half*)p_t1h, n);
    k_agg<32, true, true><<<cdiv((long long)n * 8, T), T>>>(
        (const __half*)p_t1h, (const float*)p_t1f, b1,
        (float*)p_h1f, (__half*)p_h1h, n);

    // --- layer 2: s2 = A h1 ; h2 = elu(s2@W2 + b2) ---
    k_agg<32, false, false><<<cdiv((long long)n * 8, T), T>>>(
        (const __half*)p_h1h, (const float*)p_h1f, nullptr,
        (float*)p_s2, nullptr, n);
    k_gemm<32, 64, true, true, true><<<cdiv(n, 64), 256>>>(
        (const float*)p_s2, W2, b2, (float*)p_h2f, (__half*)p_h2h, n);

    // --- layer 3: s3 = A h2 ; out = s3@W3 + b3 ---
    k_agg<64, false, false><<<cdiv((long long)n * 16, T), T>>>(
        (const __half*)p_h2h, (const float*)p_h2f, nullptr,
        (float*)p_s3, nullptr, n);
    k_gemm<64, 128, true, false, false><<<cdiv(n, 32), 256>>>(
        (const float*)p_s3, W3, b3, out, nullptr, n);
}

// round 7
// speedup vs baseline: 5.7599x; 1.6724x over previous
#include <cuda_runtime.h>
#include <cuda_fp16.h>
#include <cstdint>

#define NN 100000
#define NE 3200000
#define DEG_SCALE 33554432.0f   // 2^25 fixed-point for packed degree

// ---------------- scratch (device globals; no allocation allowed) ----------
__device__ __align__(16) unsigned long long g_pack[NN]; // {cnt<<40 | deg*2^25}
__device__ __align__(16) float g_dinv[NN];
__device__ __align__(16) int   g_cnt[NN];
__device__ __align__(16) int   g_off[NN];
__device__ __align__(16) int   g_cur[NN];
__device__ __align__(16) int   g_bsum[512];
__device__ int g_is64;

__device__ __align__(16) uint2 g_edge[NE];      // CSR payload: {src, norm bits}

__device__ __align__(16) __half g_t1h[NN * 32]; // x @ W1 (fp16)
__device__ __align__(16) __half g_h1h[NN * 32]; // elu layer-1 out (fp16)
__device__ __align__(16) float  g_s2 [NN * 32]; // A @ h1 (fp32)
__device__ __align__(16) __half g_h2h[NN * 64]; // elu layer-2 out (fp16)
__device__ __align__(16) float  g_s3 [NN * 64]; // A @ h2 (fp32)

// ---------------- dtype detect: int64 vs int32 edge_index -----------------
__global__ void k_detect(const int* __restrict__ ei32) {
    __shared__ int cnt;
    if (threadIdx.x == 0) cnt = 0;
    __syncthreads();
    int zeros = 0;
    for (int i = threadIdx.x; i < 1024; i += blockDim.x)
        if (ei32[2 * i + 1] == 0) zeros++;
    atomicAdd(&cnt, zeros);
    __syncthreads();
    if (threadIdx.x == 0) g_is64 = (cnt > 900) ? 1 : 0;
}

__device__ __forceinline__ void load_edge(const int* __restrict__ ei32,
                                          int e, int E, int n, int& r, int& c) {
    if (g_is64) {
        r = ei32[2 * (long long)e];
        c = ei32[2 * ((long long)E + e)];
    } else {
        r = ei32[e];
        c = ei32[E + e];
    }
    if ((unsigned)r >= (unsigned)n) r = 0;
    if ((unsigned)c >= (unsigned)n) c = 0;
}

// ---------------- prep ------------------------------------------------------
__global__ void k_init(int n) {
    int i = blockIdx.x * blockDim.x + threadIdx.x;
    if (i < n) g_pack[i] = (unsigned long long)DEG_SCALE;  // deg=1 (self), cnt=0
}

__global__ void k_prep(const int* __restrict__ ei32,
                       const float* __restrict__ ea, int E, int n) {
    int e = blockIdx.x * blockDim.x + threadIdx.x;
    if (e >= E) return;
    int c;
    if (g_is64) c = ei32[2 * ((long long)E + e)];
    else        c = ei32[E + e];
    if ((unsigned)c >= (unsigned)n) c = 0;
    const unsigned long long add =
        (1ULL << 40) | (unsigned long long)(fmaxf(ea[e], 0.f) * DEG_SCALE + 0.5f);
    atomicAdd(&g_pack[c], add);
}

__global__ void k_dinv(int n) {
    int i = blockIdx.x * blockDim.x + threadIdx.x;
    if (i >= n) return;
    const unsigned long long p = g_pack[i];
    g_cnt[i] = (int)(p >> 40);
    const float d = (float)(p & 0xFFFFFFFFFFULL) * (1.0f / DEG_SCALE);
    g_dinv[i] = (d > 0.0f) ? rsqrtf(fmaxf(d, 1e-30f)) : 0.0f;
}

// ---------------- 3-kernel exclusive scan of g_cnt -> g_off ----------------
__global__ void k_scan1(int n) {
    __shared__ int sh[256];
    const int t = threadIdx.x;
    const int i = blockIdx.x * 256 + t;
    int v = (i < n) ? g_cnt[i] : 0;
    sh[t] = v;
    __syncthreads();
    for (int d = 1; d < 256; d <<= 1) {
        int u = (t >= d) ? sh[t - d] : 0;
        __syncthreads();
        sh[t] += u;
        __syncthreads();
    }
    if (i < n) g_off[i] = sh[t] - v;
    if (t == 255) g_bsum[blockIdx.x] = sh[255];
}

__global__ void k_scan2(int nb) {
    __shared__ int sh[512];
    const int t = threadIdx.x;
    int v = (t < nb) ? g_bsum[t] : 0;
    sh[t] = v;
    __syncthreads();
    for (int d = 1; d < 512; d <<= 1) {
        int u = (t >= d) ? sh[t - d] : 0;
        __syncthreads();
        sh[t] += u;
        __syncthreads();
    }
    if (t < nb) g_bsum[t] = sh[t] - v;
}

__global__ void k_scan3(int n) {
    int i = blockIdx.x * 256 + threadIdx.x;
    if (i < n) g_off[i] += g_bsum[blockIdx.x];
}

// ---------------- CSR fill --------------------------------------------------
__global__ void k_fill(const int* __restrict__ ei32,
                       const float* __restrict__ ea, int E, int n) {
    int e = blockIdx.x * blockDim.x + threadIdx.x;
    if (e >= E) return;
    int r, c;
    load_edge(ei32, e, E, n, r, c);
    const int pos = atomicAdd(&g_cur[c], 1);
    const float w = g_dinv[r] * ea[e] * g_dinv[c];
    g_edge[pos] = make_uint2((unsigned)r, __float_as_uint(w));
}

// ---------------- register-tiled GEMM with fused epilogue -------------------
// 256 threads; thread tile = 4 nodes x 4 fouts; X staged transposed in smem.
template <int FIN, int FOUT, bool BIAS, bool ELU, bool WF, bool WH>
__global__ void k_gemm(const float* __restrict__ X, const float* __restrict__ W,
                       const float* __restrict__ b, float* __restrict__ Yf,
                       __half* __restrict__ Yh, int n) {
    constexpr int BX   = FOUT / 4;
    constexpr int BY   = 256 / BX;
    constexpr int NPB  = BY * 4;
    constexpr int KC   = 32;
    constexpr int XSTR = NPB + 1;

    __shared__ float Xs[KC * XSTR];
    __shared__ float Ws[KC * FOUT];

    const int tid = threadIdx.x;
    const int tx = tid % BX;
    const int ty = tid / BX;
    const int node0 = blockIdx.x * NPB;

    float acc[4][4] = {};

    for (int ck = 0; ck < FIN; ck += KC) {
#pragma unroll
        for (int t = 0; t < NPB * KC / 256; t++) {
            const int idx = t * 256 + tid;
            const int ln = idx / KC;
            const int k  = idx % KC;
            const int node = node0 + ln;
            Xs[k * XSTR + ln] = (node < n) ? X[(size_t)node * FIN + ck + k] : 0.f;
        }
#pragma unroll
        for (int t = 0; t < KC * FOUT / 256; t++) {
            const int idx = t * 256 + tid;
            Ws[idx] = W[(size_t)(ck + idx / FOUT) * FOUT + (idx % FOUT)];
        }
        __syncthreads();

#pragma unroll
        for (int k = 0; k < KC; k++) {
            const float4 wv = *(const float4*)&Ws[k * FOUT + tx * 4];
#pragma unroll
            for (int j = 0; j < 4; j++) {
                const float xv = Xs[k * XSTR + ty * 4 + j];
                acc[j][0] += xv * wv.x;
                acc[j][1] += xv * wv.y;
                acc[j][2] += xv * wv.z;
                acc[j][3] += xv * wv.w;
            }
        }
        __syncthreads();
    }

    float4 bv = make_float4(0.f, 0.f, 0.f, 0.f);
    if (BIAS) bv = *(const float4*)&b[tx * 4];

#pragma unroll
    for (int j = 0; j < 4; j++) {
        const int node = node0 + ty * 4 + j;
        if (node >= n) continue;
        float o0 = acc[j][0] + bv.x;
        float o1 = acc[j][1] + bv.y;
        float o2 = acc[j][2] + bv.z;
        float o3 = acc[j][3] + bv.w;
        if (ELU) {
            o0 = (o0 > 0.f) ? o0 : expm1f(o0);
            o1 = (o1 > 0.f) ? o1 : expm1f(o1);
            o2 = (o2 > 0.f) ? o2 : expm1f(o2);
            o3 = (o3 > 0.f) ? o3 : expm1f(o3);
        }
        if (WF) {
            float4 ov; ov.x = o0; ov.y = o1; ov.z = o2; ov.w = o3;
            *(float4*)(Yf + (size_t)node * FOUT + tx * 4) = ov;
        }
        if (WH) {
            __half2* hp = (__half2*)(Yh + (size_t)node * FOUT + tx * 4);
            hp[0] = __floats2half2_rn(o0, o1);
            hp[1] = __floats2half2_rn(o2, o3);
        }
    }
}

// ---------------- fused CSR aggregate ---------------------------------------
// out[i] = sum_{e in seg(i)} gh[src(e)]*norm(e) + gh[i]*dinv[i]^2 (+b, elu)
// F/8 lanes per node; each lane owns 8 halfs (one 16B load per edge).
template <int F, bool BE, bool WF, bool WH>
__global__ void k_agg(const __half* __restrict__ gh, const float* __restrict__ b,
                      float* __restrict__ outf, __half* __restrict__ outh, int n) {
    constexpr int LPE = F / 8;
    const long long tid = (long long)blockIdx.x * blockDim.x + threadIdx.x;
    const int node = (int)(tid / LPE);
    const int s = (int)(tid % LPE);
    if (node >= n) return;

    const int base = g_off[node];
    const int deg  = g_cnt[node];

    float a0 = 0.f, a1 = 0.f, a2 = 0.f, a3 = 0.f;
    float a4 = 0.f, a5 = 0.f, a6 = 0.f, a7 = 0.f;
    int k = 0;
#define GATH(ED)                                                               \
    {                                                                          \
        const float w_ = __uint_as_float((ED).y);                              \
        const uint4 raw_ = *(const uint4*)(gh + (size_t)(ED).x * F + s * 8);   \
        const float2 p0_ = __half22float2(*(const __half2*)&raw_.x);           \
        const float2 p1_ = __half22float2(*(const __half2*)&raw_.y);           \
        const float2 p2_ = __half22float2(*(const __half2*)&raw_.z);           \
        const float2 p3_ = __half22float2(*(const __half2*)&raw_.w);           \
        a0 += p0_.x * w_; a1 += p0_.y * w_;                                    \
        a2 += p1_.x * w_; a3 += p1_.y * w_;                                    \
        a4 += p2_.x * w_; a5 += p2_.y * w_;                                    \
        a6 += p3_.x * w_; a7 += p3_.y * w_;                                    \
    }
    for (; k + 4 <= deg; k += 4) {
        const uint2 e0 = g_edge[base + k],     e1 = g_edge[base + k + 1];
        const uint2 e2 = g_edge[base + k + 2], e3 = g_edge[base + k + 3];
        GATH(e0) GATH(e1) GATH(e2) GATH(e3)
    }
    for (; k < deg; k++) {
        const uint2 e0 = g_edge[base + k];
        GATH(e0)
    }
#undef GATH

    // self-loop (fp16 table) + optional bias/elu
    float dv = g_dinv[node]; dv *= dv;
    {
        const uint4 raw = *(const uint4*)(gh + (size_t)node * F + s * 8);
        const float2 p0 = __half22float2(*(const __half2*)&raw.x);
        const float2 p1 = __half22float2(*(const __half2*)&raw.y);
        const float2 p2 = __half22float2(*(const __half2*)&raw.z);
        const float2 p3 = __half22float2(*(const __half2*)&raw.w);
        a0 += p0.x * dv; a1 += p0.y * dv;
        a2 += p1.x * dv; a3 += p1.y * dv;
        a4 += p2.x * dv; a5 += p2.y * dv;
        a6 += p3.x * dv; a7 += p3.y * dv;
    }
    if (BE) {
        a0 += b[s * 8 + 0]; a1 += b[s * 8 + 1];
        a2 += b[s * 8 + 2]; a3 += b[s * 8 + 3];
        a4 += b[s * 8 + 4]; a5 += b[s * 8 + 5];
        a6 += b[s * 8 + 6]; a7 += b[s * 8 + 7];
        a0 = (a0 > 0.f) ? a0 : expm1f(a0);
        a1 = (a1 > 0.f) ? a1 : expm1f(a1);
        a2 = (a2 > 0.f) ? a2 : expm1f(a2);
        a3 = (a3 > 0.f) ? a3 : expm1f(a3);
        a4 = (a4 > 0.f) ? a4 : expm1f(a4);
        a5 = (a5 > 0.f) ? a5 : expm1f(a5);
        a6 = (a6 > 0.f) ? a6 : expm1f(a6);
        a7 = (a7 > 0.f) ? a7 : expm1f(a7);
    }
    if (WF) {
        float4 o0; o0.x = a0; o0.y = a1; o0.z = a2; o0.w = a3;
        float4 o1; o1.x = a4; o1.y = a5; o1.z = a6; o1.w = a7;
        float4* fp = (float4*)(outf + (size_t)node * F + s * 8);
        fp[0] = o0; fp[1] = o1;
    }
    if (WH) {
        uint4 hv;
        hv.x = __half2_raw(__floats2half2_rn(a0, a1)).x |
               ((unsigned)__half2_raw(__floats2half2_rn(a0, a1)).y << 16);
        // simpler: build via half2 stores
        __half2* hp = (__half2*)(outh + (size_t)node * F + s * 8);
        hp[0] = __floats2half2_rn(a0, a1);
        hp[1] = __floats2half2_rn(a2, a3);
        hp[2] = __floats2half2_rn(a4, a5);
        hp[3] = __floats2half2_rn(a6, a7);
    }
}

// ---------------- launch ---------------------------------------------------
static inline int cdiv(long long a, int b) { return (int)((a + b - 1) / b); }

extern "C" void kernel_launch(void* const* d_in, const int* in_sizes, int n_in,
                              void* d_out, int out_size) {
    const float* x  = (const float*)d_in[0];
    const int*   ei = (const int*)d_in[1];
    const float* ea = (const float*)d_in[2];
    const float* W1 = (const float*)d_in[3];
    const float* b1 = (const float*)d_in[4];
    const float* W2 = (const float*)d_in[5];
    const float* b2 = (const float*)d_in[6];
    const float* W3 = (const float*)d_in[7];
    const float* b3 = (const float*)d_in[8];
    float* out = (float*)d_out;

    const int n = in_sizes[0] / 128;   // 100000
    const int E = in_sizes[2];         // 3200000

    void *p_off, *p_cur, *p_t1h, *p_h1h, *p_s2, *p_h2h, *p_s3;
    cudaGetSymbolAddress(&p_off, g_off);
    cudaGetSymbolAddress(&p_cur, g_cur);
    cudaGetSymbolAddress(&p_t1h, g_t1h);
    cudaGetSymbolAddress(&p_h1h, g_h1h);
    cudaGetSymbolAddress(&p_s2,  g_s2);
    cudaGetSymbolAddress(&p_h2h, g_h2h);
    cudaGetSymbolAddress(&p_s3,  g_s3);

    const int T = 256;
    const int nb = cdiv(n, 256);

    // --- prep: degrees, dinv, CSR build ---
    k_detect<<<1, 256>>>(ei);
    k_init<<<cdiv(n, T), T>>>(n);
    k_prep<<<cdiv(E, T), T>>>(ei, ea, E, n);
    k_dinv<<<cdiv(n, T), T>>>(n);
    k_scan1<<<nb, 256>>>(n);
    k_scan2<<<1, 512>>>(nb);
    k_scan3<<<nb, 256>>>(n);
    cudaMemcpyAsync(p_cur, p_off, (size_t)n * sizeof(int),
                    cudaMemcpyDeviceToDevice);
    k_fill<<<cdiv(E, T), T>>>(ei, ea, E, n);

    // --- layer 1: t1 = x@W1 (fp16) ; h1 = elu(A t1 + b1) (fp16) ---
    k_gemm<128, 32, false, false, false, true><<<cdiv(n, 128), 256>>>(
        x, W1, nullptr, nullptr, (__half*)p_t1h, n);
    k_agg<32, true, false, true><<<cdiv((long long)n * 4, T), T>>>(
        (const __half*)p_t1h, b1, nullptr, (__half*)p_h1h, n);

    // --- layer 2: s2 = A h1 (fp32) ; h2 = elu(s2@W2 + b2) (fp16) ---
    k_agg<32, false, true, false><<<cdiv((long long)n * 4, T), T>>>(
        (const __half*)p_h1h, nullptr, (float*)p_s2, nullptr, n);
    k_gemm<32, 64, true, true, false, true><<<cdiv(n, 64), 256>>>(
        (const float*)p_s2, W2, b2, nullptr, (__half*)p_h2h, n);

    // --- layer 3: s3 = A h2 (fp32) ; out = s3@W3 + b3 ---
    k_agg<64, false, true, false><<<cdiv((long long)n * 8, T), T>>>(
        (const __half*)p_h2h, nullptr, (float*)p_s3, nullptr, n);
    k_gemm<64, 128, true, false, true, false><<<cdiv(n, 32), 256>>>(
        (const float*)p_s3, W3, b3, out, nullptr, n);
}